// round 1
// baseline (speedup 1.0000x reference)
#include <cuda_runtime.h>

#define H   64
#define NH  4
#define MA  64
#define BS  64
#define E   256    // H*NH
#define NROWS 4096 // BS*MA

// scratch (device globals: no allocation allowed)
__device__ float g_cb[NROWS * H];        // gathered c, [4096][64]
__device__ float g_u[NROWS * E];         // u = c @ Wa_pair, [4096][256]
__device__ float g_molpart[BS * 2 * H];  // per-(b,half) molecule partials

__device__ __forceinline__ long long scope_at(const void* sp, int i, bool is64) {
    return is64 ? ((const long long*)sp)[i] : (long long)((const int*)sp)[i];
}
__device__ __forceinline__ bool scope_is64(const void* sp) {
    // scope flat: [1, 2, ...] as int32 -> word1 == 2 ; as int64 -> word1 == 0
    return ((const int*)sp)[1] == 0;
}

// ---------------------------------------------------------------------------
// Kernel A: gather c_batch rows via scope, compute u = c @ Wa_pair
// grid 256, block 256; each block handles 16 rows of [4096]
// ---------------------------------------------------------------------------
__global__ void __launch_bounds__(256) kA(const float* __restrict__ inputs,
                                          const void* __restrict__ scope,
                                          const float* __restrict__ Wa_pair) {
    __shared__ float cs[16 * H];
    const bool is64 = scope_is64(scope);
    const int t = threadIdx.x, blk = blockIdx.x;

    for (int p = t; p < 16 * H; p += 256) {
        int rl = p >> 6, h = p & 63;
        int r = blk * 16 + rl;
        long long s = scope_at(scope, r, is64);
        float v = inputs[s * H + h];
        cs[p] = v;
        g_cb[r * H + h] = v;
    }
    __syncthreads();

    const int e = t;  // 0..255, one output column per thread
    float acc[16];
#pragma unroll
    for (int k = 0; k < 16; k++) acc[k] = 0.f;
#pragma unroll 4
    for (int h = 0; h < H; h++) {
        float w = __ldg(Wa_pair + h * E + e);
#pragma unroll
        for (int k = 0; k < 16; k++) acc[k] = fmaf(cs[k * H + h], w, acc[k]);
    }
#pragma unroll
    for (int k = 0; k < 16; k++) g_u[(blk * 16 + k) * E + e] = acc[k];
}

// ---------------------------------------------------------------------------
// Kernel B: pairwise attention + c_sum + projection + partial reductions
// grid (64, 2): (b, i-half of 32). 512 threads = 16 warps, 2 i per warp.
// dyn smem: cb[64*64] | u[64*256] | csum[32*256] | red[8*64]
// ---------------------------------------------------------------------------
__global__ void __launch_bounds__(512, 1) kB(const void* __restrict__ scope,
                                             const float* __restrict__ Wa_score,
                                             const float* __restrict__ Wp,
                                             float* __restrict__ d_out) {
    extern __shared__ float sm[];
    float* cb_s   = sm;                    // 4096
    float* u_s    = cb_s + MA * H;         // 16384
    float* csum_s = u_s + MA * E;          // 8192
    float* red_s  = csum_s + 32 * E;       // 512

    const bool is64 = scope_is64(scope);
    const int b = blockIdx.x, half = blockIdx.y;
    const int t = threadIdx.x, l = t & 31, wid = t >> 5;

    // stage cb[b] and u[b] through smem (float4)
    {
        const float4* sc = (const float4*)(g_cb + b * MA * H);
        float4* dc = (float4*)cb_s;
        for (int p = t; p < MA * H / 4; p += 512) dc[p] = sc[p];
        const float4* su = (const float4*)(g_u + b * MA * E);
        float4* du = (float4*)u_s;
        for (int p = t; p < MA * E / 4; p += 512) du[p] = su[p];
    }
    __syncthreads();

    // lane l owns elements e = l + 32k  (so head n = e&3 = l&3 is lane-constant)
    float ws[8];
#pragma unroll
    for (int k = 0; k < 8; k++) ws[k] = __ldg(Wa_score + l + 32 * k);

    const int hsub = l >> 2;  // 0..7, h base for csum accumulation

    for (int rep = 0; rep < 2; rep++) {
        const int il = wid + rep * 16;     // local i within the 32-row half
        const int i  = half * 32 + il;     // i within molecule
        float ui[8], csum[8];
#pragma unroll
        for (int k = 0; k < 8; k++) { ui[k] = u_s[i * E + l + 32 * k]; csum[k] = 0.f; }

        for (int j = 0; j < MA; j++) {
            float s = 0.f;
            const float* uj = u_s + j * E;
#pragma unroll
            for (int k = 0; k < 8; k++) {
                float v = fmaxf(ui[k] + uj[l + 32 * k], 0.f);
                s = fmaf(v, ws[k], s);
            }
            // reduce over the 8 lanes sharing head n = l&3 (bits 2..4)
            s += __shfl_xor_sync(0xffffffffu, s, 4);
            s += __shfl_xor_sync(0xffffffffu, s, 8);
            s += __shfl_xor_sync(0xffffffffu, s, 16);
            float a = 1.f / (1.f + __expf(-s));  // sigmoid
            const float* cj = cb_s + j * H;
#pragma unroll
            for (int k = 0; k < 8; k++)
                csum[k] = fmaf(a, cj[hsub + 8 * k], csum[k]);
        }
#pragma unroll
        for (int k = 0; k < 8; k++) csum_s[il * E + l + 32 * k] = csum[k];
    }
    __syncthreads();

    // projection: A[r][hh] = sum_e csum[r][e] * Wp[e][hh]
    const int hh = t & 63, g = t >> 6;  // g in 0..7, 4 rows per thread
    float acc[4] = {0.f, 0.f, 0.f, 0.f};
#pragma unroll 4
    for (int e = 0; e < E; e++) {
        float w = __ldg(Wp + e * H + hh);
#pragma unroll
        for (int m = 0; m < 4; m++)
            acc[m] = fmaf(csum_s[(g + 8 * m) * E + e], w, acc[m]);
    }

    // scatter flat rows: flat[scope[b*64+i]] = A[b,i]  (scope==0 -> pad, skip)
    float* flat = d_out + BS * H;
#pragma unroll
    for (int m = 0; m < 4; m++) {
        int il = g + 8 * m;
        int ig = b * MA + half * 32 + il;
        long long s = scope_at(scope, ig, is64);
        if (s > 0) flat[s * H + hh] = acc[m];
    }

    // molecule partial for this (b, half)
    red_s[g * H + hh] = acc[0] + acc[1] + acc[2] + acc[3];
    __syncthreads();
    if (t < 64) {
        float sum = 0.f;
#pragma unroll
        for (int g2 = 0; g2 < 8; g2++) sum += red_s[g2 * H + t];
        g_molpart[(b * 2 + half) * H + t] = sum;
    }
}

// ---------------------------------------------------------------------------
// Kernel C: c_mol = sum of 2 half-partials; zero flat row 0
// ---------------------------------------------------------------------------
__global__ void __launch_bounds__(256) kC(float* __restrict__ d_out) {
    int t = blockIdx.x * 256 + threadIdx.x;
    if (t < BS * H) {
        int b = t >> 6, hh = t & 63;
        d_out[t] = g_molpart[(b * 2) * H + hh] + g_molpart[(b * 2 + 1) * H + hh];
    }
    if (t < H) d_out[BS * H + t] = 0.f;  // flat row 0 (pad row)
}

// ---------------------------------------------------------------------------
extern "C" void kernel_launch(void* const* d_in, const int* in_sizes, int n_in,
                              void* d_out, int out_size) {
    const float* inputs   = (const float*)d_in[0];
    const void*  scope    = d_in[1];
    // d_in[2] = scope_rev_tensor (unused: scatter via scope is its inverse)
    const float* Wa_pair  = (const float*)d_in[3];
    const float* Wa_score = (const float*)d_in[4];
    const float* Wp       = (const float*)d_in[5];
    float* out = (float*)d_out;

    const int smemB = (MA * H + MA * E + 32 * E + 8 * H) * (int)sizeof(float); // 116736
    cudaFuncSetAttribute(kB, cudaFuncAttributeMaxDynamicSharedMemorySize, smemB);

    kA<<<256, 256>>>(inputs, scope, Wa_pair);
    kB<<<dim3(BS, 2), 512, smemB>>>(scope, Wa_score, Wp, out);
    kC<<<16, 256>>>(out);
}

// round 2
// speedup vs baseline: 1.1557x; 1.1557x over previous
#include <cuda_runtime.h>

#define H   64
#define NH  4
#define MA  64
#define BS  64
#define E   256    // H*NH
#define MAXROWS 4096

// scratch (device globals: no allocation allowed)
__device__ float g_u[MAXROWS * E];        // u rows, PERMUTED layout p=(e&31)*8+(e>>5)
__device__ float g_molpart[BS * 4 * H];   // per-(b,quarter) molecule partials

__device__ __forceinline__ long long scope_at(const void* sp, int i, bool is64) {
    return is64 ? ((const long long*)sp)[i] : (long long)((const int*)sp)[i];
}
__device__ __forceinline__ bool scope_is64(const void* sp) {
    // scope flat: [1, 2, ...] as int32 -> word1 == 2 ; as int64 -> word1 == 0
    return ((const int*)sp)[1] == 0;
}
__device__ __forceinline__ float sigmoid_fast(float s) {
    float t;
    asm("tanh.approx.f32 %0, %1;" : "=f"(t) : "f"(0.5f * s));
    return fmaf(0.5f, t, 0.5f);   // 0.5*(1+tanh(s/2)) == sigmoid(s)
}

// ---------------------------------------------------------------------------
// Kernel A: u_flat = inputs @ Wa_pair over all N+1 flat rows, permuted store.
// grid ceil(n1/16) x 256 threads; thread = 4 rows x 4 e-cols.
// ---------------------------------------------------------------------------
__global__ void __launch_bounds__(256) kA(const float* __restrict__ inputs,
                                          const float* __restrict__ Wa_pair,
                                          int n1) {
    __shared__ float cs[16 * H];
    const int t = threadIdx.x, blk = blockIdx.x;

    // load 16 rows x 64 floats = 256 float4, one per thread
    {
        int row = t >> 4, f4 = t & 15;
        int r = blk * 16 + row;
        float4 z = make_float4(0.f, 0.f, 0.f, 0.f);
        ((float4*)cs)[t] = (r < n1) ? ((const float4*)(inputs + (size_t)r * H))[f4] : z;
    }
    __syncthreads();

    const int eg = t & 63, rg = t >> 6;   // e-group (4 cols), row-group (4 rows)
    const int e0 = eg * 4;
    float4 acc[4];
#pragma unroll
    for (int m = 0; m < 4; m++) acc[m] = make_float4(0.f, 0.f, 0.f, 0.f);

#pragma unroll 8
    for (int h = 0; h < H; h++) {
        float4 w = __ldg((const float4*)(Wa_pair + h * E + e0));
#pragma unroll
        for (int m = 0; m < 4; m++) {
            float c = cs[(rg * 4 + m) * H + h];
            acc[m].x = fmaf(c, w.x, acc[m].x);
            acc[m].y = fmaf(c, w.y, acc[m].y);
            acc[m].z = fmaf(c, w.z, acc[m].z);
            acc[m].w = fmaf(c, w.w, acc[m].w);
        }
    }

    // permuted scalar stores (L2-resident scratch; sector inefficiency harmless)
#pragma unroll
    for (int m = 0; m < 4; m++) {
        int rr = blk * 16 + rg * 4 + m;
        if (rr < n1) {
            float* dst = g_u + (size_t)rr * E;
            float av[4] = {acc[m].x, acc[m].y, acc[m].z, acc[m].w};
#pragma unroll
            for (int c = 0; c < 4; c++) {
                int e = e0 + c;
                dst[(e & 31) * 8 + (e >> 5)] = av[c];
            }
        }
    }
}

// ---------------------------------------------------------------------------
// Kernel B: pairwise attention + c_sum + projection + partials.
// grid (64, 4): (b, quarter of 16 i-rows). 512 threads = 16 warps, 1 i per warp.
// dyn smem: up_s[64*256] | cbp_s[64*64]  (cbp reused as csum[16*256];
//           up_s reused as red[16*64])   => 80 KB -> 2 blocks/SM.
// ---------------------------------------------------------------------------
__global__ void __launch_bounds__(512, 2) kB(const float* __restrict__ inputs,
                                             const void* __restrict__ scope,
                                             const float* __restrict__ Wa_score,
                                             const float* __restrict__ Wp,
                                             float* __restrict__ d_out) {
    extern __shared__ float sm[];
    float* up_s  = sm;              // 64*256 floats (permuted rows)
    float* cbp_s = sm + MA * E;     // 64*64 floats (permuted), later csum 16*256

    const bool is64 = scope_is64(scope);
    const int b = blockIdx.x, qq = blockIdx.y;
    const int t = threadIdx.x, l = t & 31, wid = t >> 5;

    // stage u rows (already permuted in gmem) via scope: float4 both sides
#pragma unroll
    for (int it = 0; it < 8; it++) {
        int Q = t + 512 * it;            // 64 rows * 64 quads
        int j = Q >> 6, qd = Q & 63;
        long long s = scope_at(scope, b * MA + j, is64);
        ((float4*)up_s)[Q] = ((const float4*)(g_u + (size_t)s * E))[qd];
    }
    // stage cb permuted: p=(h&7)*8+(h>>3); strided gmem reads, STS.128 conflict-free
#pragma unroll
    for (int it = 0; it < 2; it++) {
        int Q = t + 512 * it;            // 64 rows * 16 quads
        int j = Q >> 4, qd = Q & 15;
        long long s = scope_at(scope, b * MA + j, is64);
        const float* src = inputs + (size_t)s * H;
        int hb = 32 * (qd & 1) + (qd >> 1);
        float4 v;
        v.x = src[hb];  v.y = src[hb + 8];  v.z = src[hb + 16];  v.w = src[hb + 24];
        ((float4*)cbp_s)[Q] = v;
    }
    __syncthreads();

    const int i = qq * 16 + wid;         // this warp's i row
    const int hsub = l >> 2;             // 0..7
    // lane l owns e = l + 32k (head n = l&3 lane-constant -> 3-shuffle reduce)
    float ws[8];
#pragma unroll
    for (int k = 0; k < 8; k++) ws[k] = __ldg(Wa_score + l + 32 * k);

    float4 ui0 = ((const float4*)(up_s + i * E))[2 * l];
    float4 ui1 = ((const float4*)(up_s + i * E))[2 * l + 1];
    float csum[8];
#pragma unroll
    for (int k = 0; k < 8; k++) csum[k] = 0.f;

#pragma unroll 2
    for (int j = 0; j < MA; j++) {
        const float4* ur = (const float4*)(up_s + j * E);
        float4 a0 = ur[2 * l], a1 = ur[2 * l + 1];
        float v, s0, s1;
        v = fmaxf(ui0.x + a0.x, 0.f); s0 = v * ws[0];
        v = fmaxf(ui0.y + a0.y, 0.f); s1 = v * ws[1];
        v = fmaxf(ui0.z + a0.z, 0.f); s0 = fmaf(v, ws[2], s0);
        v = fmaxf(ui0.w + a0.w, 0.f); s1 = fmaf(v, ws[3], s1);
        v = fmaxf(ui1.x + a1.x, 0.f); s0 = fmaf(v, ws[4], s0);
        v = fmaxf(ui1.y + a1.y, 0.f); s1 = fmaf(v, ws[5], s1);
        v = fmaxf(ui1.z + a1.z, 0.f); s0 = fmaf(v, ws[6], s0);
        v = fmaxf(ui1.w + a1.w, 0.f); s1 = fmaf(v, ws[7], s1);
        float s = s0 + s1;
        s += __shfl_xor_sync(0xffffffffu, s, 4);
        s += __shfl_xor_sync(0xffffffffu, s, 8);
        s += __shfl_xor_sync(0xffffffffu, s, 16);
        float att = sigmoid_fast(s);
        const float4* cr = (const float4*)(cbp_s + j * H);
        float4 c0 = cr[2 * hsub], c1 = cr[2 * hsub + 1];
        csum[0] = fmaf(att, c0.x, csum[0]);
        csum[1] = fmaf(att, c0.y, csum[1]);
        csum[2] = fmaf(att, c0.z, csum[2]);
        csum[3] = fmaf(att, c0.w, csum[3]);
        csum[4] = fmaf(att, c1.x, csum[4]);
        csum[5] = fmaf(att, c1.y, csum[5]);
        csum[6] = fmaf(att, c1.z, csum[6]);
        csum[7] = fmaf(att, c1.w, csum[7]);
    }

    __syncthreads();                      // all warps done reading cbp_s/up_s
    float* csum_s = cbp_s;                // reuse: 16 rows x 256 (logical e order)
#pragma unroll
    for (int k = 0; k < 8; k++) csum_s[wid * E + l + 32 * k] = csum[k];
    __syncthreads();

    // projection: thread -> row g=wid, cols (2l, 2l+1)
    const int hh2 = 2 * l;
    float acc0 = 0.f, acc1 = 0.f;
    const float4* crow = (const float4*)(csum_s + wid * E);
#pragma unroll 4
    for (int e4 = 0; e4 < E; e4 += 4) {
        float4 c4 = crow[e4 >> 2];        // broadcast LDS.128
        float2 w0 = __ldg((const float2*)(Wp + (e4 + 0) * H + hh2));
        float2 w1 = __ldg((const float2*)(Wp + (e4 + 1) * H + hh2));
        float2 w2 = __ldg((const float2*)(Wp + (e4 + 2) * H + hh2));
        float2 w3 = __ldg((const float2*)(Wp + (e4 + 3) * H + hh2));
        acc0 = fmaf(c4.x, w0.x, acc0); acc1 = fmaf(c4.x, w0.y, acc1);
        acc0 = fmaf(c4.y, w1.x, acc0); acc1 = fmaf(c4.y, w1.y, acc1);
        acc0 = fmaf(c4.z, w2.x, acc0); acc1 = fmaf(c4.z, w2.y, acc1);
        acc0 = fmaf(c4.w, w3.x, acc0); acc1 = fmaf(c4.w, w3.y, acc1);
    }

    // scatter flat rows: flat[scope[b*64+i]] = A[b,i] (scope==0 -> pad, skip)
    float* flat = d_out + BS * H;
    long long sc = scope_at(scope, b * MA + i, is64);
    if (sc > 0) {
        float2 o = make_float2(acc0, acc1);
        *(float2*)(flat + sc * H + hh2) = o;
    }

    // molecule partial for this (b, quarter)
    float* red_s = up_s;                  // reuse (disjoint from csum_s)
    red_s[wid * H + hh2]     = acc0;
    red_s[wid * H + hh2 + 1] = acc1;
    __syncthreads();
    if (t < H) {
        float sum = 0.f;
#pragma unroll
        for (int g2 = 0; g2 < 16; g2++) sum += red_s[g2 * H + t];
        g_molpart[(b * 4 + qq) * H + t] = sum;
    }
}

// ---------------------------------------------------------------------------
// Kernel C: c_mol = sum of 4 quarter-partials; zero flat row 0
// ---------------------------------------------------------------------------
__global__ void __launch_bounds__(256) kC(float* __restrict__ d_out) {
    int t = blockIdx.x * 256 + threadIdx.x;
    if (t < BS * H) {
        int b = t >> 6, hh = t & 63;
        float s = 0.f;
#pragma unroll
        for (int q = 0; q < 4; q++) s += g_molpart[(b * 4 + q) * H + hh];
        d_out[t] = s;
    }
    if (t < H) d_out[BS * H + t] = 0.f;   // flat row 0 (pad row)
}

// ---------------------------------------------------------------------------
extern "C" void kernel_launch(void* const* d_in, const int* in_sizes, int n_in,
                              void* d_out, int out_size) {
    const float* inputs   = (const float*)d_in[0];
    const void*  scope    = d_in[1];
    // d_in[2] = scope_rev_tensor (unused: scatter via scope is its inverse)
    const float* Wa_pair  = (const float*)d_in[3];
    const float* Wa_score = (const float*)d_in[4];
    const float* Wp       = (const float*)d_in[5];
    float* out = (float*)d_out;

    const int n1 = in_sizes[0] / H;                         // N+1 flat rows
    const int smemB = (MA * E + MA * H) * (int)sizeof(float);  // 81920 B
    cudaFuncSetAttribute(kB, cudaFuncAttributeMaxDynamicSharedMemorySize, smemB);

    kA<<<(n1 + 15) / 16, 256>>>(inputs, Wa_pair, n1);
    kB<<<dim3(BS, 4), 512, smemB>>>(inputs, scope, Wa_score, Wp, out);
    kC<<<16, 256>>>(out);
}

// round 4
// speedup vs baseline: 1.4081x; 1.2184x over previous
#include <cuda_runtime.h>

#define H   64
#define NH  4
#define MA  64
#define BS  64
#define E   256    // H*NH
#define MAXROWS 4096

// scratch (device globals: no allocation allowed)
__device__ float g_u[MAXROWS * E];       // u rows, PERMUTED: pos p = l*8+k holds e = l+32k
__device__ float g_csum[BS * MA * E];    // csum rows, same permuted layout
__device__ float g_molpart[BS * 2 * H];  // per-(b,half) molecule partials

__device__ __forceinline__ long long scope_at(const void* sp, int i, bool is64) {
    return is64 ? ((const long long*)sp)[i] : (long long)((const int*)sp)[i];
}
__device__ __forceinline__ bool scope_is64(const void* sp) {
    // scope flat: [1, 2, ...]; int32 -> word1 == 2 ; int64 -> word1 == 0
    return ((const int*)sp)[1] == 0;
}
__device__ __forceinline__ float sigmoid_fast(float s) {
    float t;
    asm("tanh.approx.f32 %0, %1;" : "=f"(t) : "f"(0.5f * s));
    return fmaf(0.5f, t, 0.5f);   // 0.5*(1+tanh(s/2)) == sigmoid(s)
}
__device__ __forceinline__ unsigned long long pack2(float x) {
    unsigned r = __float_as_uint(x);
    unsigned long long o;
    asm("mov.b64 %0, {%1, %1};" : "=l"(o) : "r"(r));
    return o;
}
#define FMA2(acc, a, b) asm("fma.rn.f32x2 %0, %1, %2, %0;" : "+l"(acc) : "l"(a), "l"(b))

// ---------------------------------------------------------------------------
// Kernel A: u_flat = inputs @ Wa_pair over all N+1 flat rows, permuted store.
// Also zeroes flat output row 0.
// ---------------------------------------------------------------------------
__global__ void __launch_bounds__(256) kA(const float* __restrict__ inputs,
                                          const float* __restrict__ Wa_pair,
                                          int n1, float* __restrict__ d_out) {
    __shared__ float cs[16 * H];
    const int t = threadIdx.x, blk = blockIdx.x;

    if (blk == 0 && t < 16)  // flat row 0 = pad row -> zeros
        ((float4*)(d_out + BS * H))[t] = make_float4(0.f, 0.f, 0.f, 0.f);

    {
        int row = t >> 4, f4 = t & 15;
        int r = blk * 16 + row;
        float4 z = make_float4(0.f, 0.f, 0.f, 0.f);
        ((float4*)cs)[t] = (r < n1) ? ((const float4*)(inputs + (size_t)r * H))[f4] : z;
    }
    __syncthreads();

    const int eg = t & 63, rg = t >> 6;
    const int e0 = eg * 4;
    float4 acc[4];
#pragma unroll
    for (int m = 0; m < 4; m++) acc[m] = make_float4(0.f, 0.f, 0.f, 0.f);

#pragma unroll 8
    for (int h = 0; h < H; h++) {
        float4 w = __ldg((const float4*)(Wa_pair + h * E + e0));
#pragma unroll
        for (int m = 0; m < 4; m++) {
            float c = cs[(rg * 4 + m) * H + h];
            acc[m].x = fmaf(c, w.x, acc[m].x);
            acc[m].y = fmaf(c, w.y, acc[m].y);
            acc[m].z = fmaf(c, w.z, acc[m].z);
            acc[m].w = fmaf(c, w.w, acc[m].w);
        }
    }

#pragma unroll
    for (int m = 0; m < 4; m++) {
        int rr = blk * 16 + rg * 4 + m;
        if (rr < n1) {
            float* dst = g_u + (size_t)rr * E;
            float av[4] = {acc[m].x, acc[m].y, acc[m].z, acc[m].w};
#pragma unroll
            for (int c = 0; c < 4; c++) {
                int e = e0 + c;
                dst[(e & 31) * 8 + (e >> 5)] = av[c];  // p = l*8+k for e=l+32k
            }
        }
    }
}

// ---------------------------------------------------------------------------
// Kernel B: pairwise attention + c_sum -> g_csum (permuted).
// grid (64, 4): (b, quarter). 256 threads = 8 warps; each warp handles 2 i.
// dyn smem: up_s[64*256] + cbp_s[64*64] = 80 KB -> 2 blocks/SM.
// ---------------------------------------------------------------------------
__global__ void __launch_bounds__(256) kB(const float* __restrict__ inputs,
                                          const void* __restrict__ scope,
                                          const float* __restrict__ Wa_score) {
    extern __shared__ float sm[];
    float* up_s  = sm;              // 64 rows x 256 (permuted)
    float* cbp_s = sm + MA * E;     // 64 rows x 64  (permuted: pos 8*hsub+k holds h=hsub+8k)

    const bool is64 = scope_is64(scope);
    const int b = blockIdx.x, qq = blockIdx.y;
    const int t = threadIdx.x, l = t & 31, wid = t >> 5;

    // stage u rows (already permuted in gmem) via scope: float4 both sides
#pragma unroll
    for (int it = 0; it < 16; it++) {
        int Q = t + 256 * it;            // 64 rows * 64 quads
        int j = Q >> 6, qd = Q & 63;
        long long s = scope_at(scope, b * MA + j, is64);
        ((float4*)up_s)[Q] = ((const float4*)(g_u + (size_t)s * E))[qd];
    }
    // stage c permuted
#pragma unroll
    for (int it = 0; it < 4; it++) {
        int Q = t + 256 * it;            // 64 rows * 16 quads
        int j = Q >> 4, qd = Q & 15;
        long long s = scope_at(scope, b * MA + j, is64);
        const float* src = inputs + (size_t)s * H;
        int hb = 32 * (qd & 1) + (qd >> 1);
        float4 v;
        v.x = src[hb];  v.y = src[hb + 8];  v.z = src[hb + 16];  v.w = src[hb + 24];
        ((float4*)cbp_s)[Q] = v;
    }
    __syncthreads();

    // lane l owns e = l + 32k  (head n = l&3 lane-constant -> 3-shuffle reduce)
    float ws[8];
#pragma unroll
    for (int k = 0; k < 8; k++) ws[k] = __ldg(Wa_score + l + 32 * k);

    const int hsub = l >> 2;
    const int i0 = qq * 16 + wid, i1 = i0 + 8;

    const float4* uiA = (const float4*)(up_s + i0 * E);
    float4 A0 = uiA[2 * l], A1 = uiA[2 * l + 1];
    const float4* uiB = (const float4*)(up_s + i1 * E);
    float4 B0 = uiB[2 * l], B1 = uiB[2 * l + 1];

    unsigned long long csA[4] = {0, 0, 0, 0}, csB[4] = {0, 0, 0, 0};

#pragma unroll 2
    for (int j = 0; j < MA; j++) {
        const float4* ur = (const float4*)(up_s + j * E);
        float4 a0 = ur[2 * l], a1 = ur[2 * l + 1];
        float v, sA0, sA1, sB0, sB1;
        v = fmaxf(A0.x + a0.x, 0.f); sA0 = v * ws[0];
        v = fmaxf(A0.y + a0.y, 0.f); sA1 = v * ws[1];
        v = fmaxf(A0.z + a0.z, 0.f); sA0 = fmaf(v, ws[2], sA0);
        v = fmaxf(A0.w + a0.w, 0.f); sA1 = fmaf(v, ws[3], sA1);
        v = fmaxf(A1.x + a1.x, 0.f); sA0 = fmaf(v, ws[4], sA0);
        v = fmaxf(A1.y + a1.y, 0.f); sA1 = fmaf(v, ws[5], sA1);
        v = fmaxf(A1.z + a1.z, 0.f); sA0 = fmaf(v, ws[6], sA0);
        v = fmaxf(A1.w + a1.w, 0.f); sA1 = fmaf(v, ws[7], sA1);

        v = fmaxf(B0.x + a0.x, 0.f); sB0 = v * ws[0];
        v = fmaxf(B0.y + a0.y, 0.f); sB1 = v * ws[1];
        v = fmaxf(B0.z + a0.z, 0.f); sB0 = fmaf(v, ws[2], sB0);
        v = fmaxf(B0.w + a0.w, 0.f); sB1 = fmaf(v, ws[3], sB1);
        v = fmaxf(B1.x + a1.x, 0.f); sB0 = fmaf(v, ws[4], sB0);
        v = fmaxf(B1.y + a1.y, 0.f); sB1 = fmaf(v, ws[5], sB1);
        v = fmaxf(B1.z + a1.z, 0.f); sB0 = fmaf(v, ws[6], sB0);
        v = fmaxf(B1.w + a1.w, 0.f); sB1 = fmaf(v, ws[7], sB1);

        float sA = sA0 + sA1, sB = sB0 + sB1;
        sA += __shfl_xor_sync(0xffffffffu, sA, 4);
        sB += __shfl_xor_sync(0xffffffffu, sB, 4);
        sA += __shfl_xor_sync(0xffffffffu, sA, 8);
        sB += __shfl_xor_sync(0xffffffffu, sB, 8);
        sA += __shfl_xor_sync(0xffffffffu, sA, 16);
        sB += __shfl_xor_sync(0xffffffffu, sB, 16);

        unsigned long long attA = pack2(sigmoid_fast(sA));
        unsigned long long attB = pack2(sigmoid_fast(sB));

        const ulonglong2* cr = (const ulonglong2*)(cbp_s + j * H);
        ulonglong2 c01 = cr[2 * hsub], c23 = cr[2 * hsub + 1];
        FMA2(csA[0], attA, c01.x);  FMA2(csA[1], attA, c01.y);
        FMA2(csA[2], attA, c23.x);  FMA2(csA[3], attA, c23.y);
        FMA2(csB[0], attB, c01.x);  FMA2(csB[1], attB, c01.y);
        FMA2(csB[2], attB, c23.x);  FMA2(csB[3], attB, c23.y);
    }

    // store csum rows permuted: lane l -> positions l*8 .. l*8+7
    {
        ulonglong2 v;
        float* oA = g_csum + (size_t)(b * MA + i0) * E + l * 8;
        v.x = csA[0]; v.y = csA[1]; ((ulonglong2*)oA)[0] = v;
        v.x = csA[2]; v.y = csA[3]; ((ulonglong2*)oA)[1] = v;
        float* oB = g_csum + (size_t)(b * MA + i1) * E + l * 8;
        v.x = csB[0]; v.y = csB[1]; ((ulonglong2*)oB)[0] = v;
        v.x = csB[2]; v.y = csB[3]; ((ulonglong2*)oB)[1] = v;
    }
}

// ---------------------------------------------------------------------------
// Kernel D: projection A = csum @ Wp (+ scatter flat + molecule partials).
// grid 128 = (b, half of 32 rows). 256 threads; thread = 2 rows x 4 cols.
// dyn smem: wp_s[256*64] (un-permuted to match csum layout) + cs_s[32*256] = 96 KB.
// ---------------------------------------------------------------------------
__global__ void __launch_bounds__(256) kD(const void* __restrict__ scope,
                                          const float* __restrict__ Wp,
                                          float* __restrict__ d_out) {
    extern __shared__ float sm[];
    float* wp_s = sm;            // 256 x 64, row p holds Wp row e(p)
    float* cs_s = sm + E * H;    // 32 x 256

    const bool is64 = scope_is64(scope);
    const int b = blockIdx.x >> 1, half = blockIdx.x & 1;
    const int t = threadIdx.x;

    // stage Wp with permutation matching csum storage: e(p) = (p>>3) + 32*(p&7)
#pragma unroll
    for (int it = 0; it < 16; it++) {
        int q = t + 256 * it;            // 256 p * 16 quads
        int p = q >> 4, quad = q & 15;
        int e = (p >> 3) + 32 * (p & 7);
        ((float4*)wp_s)[q] = __ldg(((const float4*)Wp) + e * 16 + quad);
    }
    // stage 32 csum rows (contiguous)
    {
        const float4* src = (const float4*)(g_csum + (size_t)(b * MA + half * 32) * E);
#pragma unroll
        for (int it = 0; it < 8; it++) ((float4*)cs_s)[t + 256 * it] = src[t + 256 * it];
    }
    __syncthreads();

    const int cg = t & 15, rg = t >> 4;   // 16 col-groups x 16 row-groups
    const int c0 = cg * 4, r0 = rg * 2;
    float4 acc0 = make_float4(0.f, 0.f, 0.f, 0.f);
    float4 acc1 = make_float4(0.f, 0.f, 0.f, 0.f);

#pragma unroll 4
    for (int p = 0; p < E; p++) {
        float4 w = ((const float4*)wp_s)[p * 16 + cg];
        float ca = cs_s[r0 * E + p];
        float cb = cs_s[(r0 + 1) * E + p];
        acc0.x = fmaf(ca, w.x, acc0.x);  acc0.y = fmaf(ca, w.y, acc0.y);
        acc0.z = fmaf(ca, w.z, acc0.z);  acc0.w = fmaf(ca, w.w, acc0.w);
        acc1.x = fmaf(cb, w.x, acc1.x);  acc1.y = fmaf(cb, w.y, acc1.y);
        acc1.z = fmaf(cb, w.z, acc1.z);  acc1.w = fmaf(cb, w.w, acc1.w);
    }

    // scatter flat rows: flat[scope[b*64+r]] = A[b,r]  (scope==0 -> pad, skip)
    float* flat = d_out + BS * H;
    {
        int r = half * 32 + r0;
        long long s0 = scope_at(scope, b * MA + r, is64);
        long long s1 = scope_at(scope, b * MA + r + 1, is64);
        if (s0 > 0) *((float4*)(flat + s0 * H + c0)) = acc0;
        if (s1 > 0) *((float4*)(flat + s1 * H + c0)) = acc1;
    }

    __syncthreads();                     // done reading cs_s -> reuse as reduction buf
    float* red = cs_s;                   // 16 x 64
    {
        float4 s2;
        s2.x = acc0.x + acc1.x; s2.y = acc0.y + acc1.y;
        s2.z = acc0.z + acc1.z; s2.w = acc0.w + acc1.w;
        *((float4*)(red + rg * H + c0)) = s2;
    }
    __syncthreads();
    if (t < H) {
        float s = 0.f;
#pragma unroll
        for (int g = 0; g < 16; g++) s += red[g * H + t];
        g_molpart[(b * 2 + half) * H + t] = s;
    }
}

// ---------------------------------------------------------------------------
// Kernel C: c_mol = sum of 2 half-partials
// ---------------------------------------------------------------------------
__global__ void __launch_bounds__(256) kC(float* __restrict__ d_out) {
    int t = blockIdx.x * 256 + threadIdx.x;
    if (t < BS * H) {
        int b = t >> 6, hh = t & 63;
        d_out[t] = g_molpart[(b * 2) * H + hh] + g_molpart[(b * 2 + 1) * H + hh];
    }
}

// ---------------------------------------------------------------------------
extern "C" void kernel_launch(void* const* d_in, const int* in_sizes, int n_in,
                              void* d_out, int out_size) {
    const float* inputs   = (const float*)d_in[0];
    const void*  scope    = d_in[1];
    // d_in[2] = scope_rev_tensor (unused: scatter via scope is its inverse)
    const float* Wa_pair  = (const float*)d_in[3];
    const float* Wa_score = (const float*)d_in[4];
    const float* Wp       = (const float*)d_in[5];
    float* out = (float*)d_out;

    const int n1 = in_sizes[0] / H;                           // N+1 flat rows
    const int smemB = (MA * E + MA * H) * (int)sizeof(float); // 81920 B
    const int smemD = (E * H + 32 * E) * (int)sizeof(float);  // 98304 B
    cudaFuncSetAttribute(kB, cudaFuncAttributeMaxDynamicSharedMemorySize, smemB);
    cudaFuncSetAttribute(kD, cudaFuncAttributeMaxDynamicSharedMemorySize, smemD);

    kA<<<(n1 + 15) / 16, 256>>>(inputs, Wa_pair, n1, out);
    kB<<<dim3(BS, 4), 256, smemB>>>(inputs, scope, Wa_score);
    kD<<<BS * 2, 256, smemD>>>(scope, Wp, out);
    kC<<<16, 256>>>(out);
}

// round 5
// speedup vs baseline: 1.5093x; 1.0718x over previous
#include <cuda_runtime.h>

#define H   64
#define NH  4
#define MA  64
#define BS  64
#define E   256    // H*NH
#define MAXROWS 4096

// scratch (device globals: no allocation allowed)
// P layout for E-vectors: element e (l=e&31, k=e>>5) stored at
//   p = (k>>2)*128 + 4*l + (k&3)
// so lane l's 8 elements are two float4s at quads l and 32+l (conflict-free LDS).
__device__ float g_u[MAXROWS * E];
__device__ float g_csum[BS * MA * E];    // same P layout

__device__ __forceinline__ long long scope_at(const void* sp, int i, bool is64) {
    return is64 ? ((const long long*)sp)[i] : (long long)((const int*)sp)[i];
}
__device__ __forceinline__ bool scope_is64(const void* sp) {
    // scope flat: [1, 2, ...]; int32 -> word1 == 2 ; int64 -> word1 == 0
    return ((const int*)sp)[1] == 0;
}
__device__ __forceinline__ float sigmoid_fast(float s) {
    float t;
    asm("tanh.approx.f32 %0, %1;" : "=f"(t) : "f"(0.5f * s));
    return fmaf(0.5f, t, 0.5f);   // 0.5*(1+tanh(s/2)) == sigmoid(s)
}
__device__ __forceinline__ unsigned long long pack2(float x) {
    unsigned r = __float_as_uint(x);
    unsigned long long o;
    asm("mov.b64 %0, {%1, %1};" : "=l"(o) : "r"(r));
    return o;
}
#define FMA2(acc, a, b) asm("fma.rn.f32x2 %0, %1, %2, %0;" : "+l"(acc) : "l"(a), "l"(b))

// ---------------------------------------------------------------------------
// Kernel A: u_flat = inputs @ Wa_pair over N+1 flat rows, P-layout store.
// Also zeroes the c_mol region and flat row 0 of d_out (atomics accumulate later).
// ---------------------------------------------------------------------------
__global__ void __launch_bounds__(256) kA(const float* __restrict__ inputs,
                                          const float* __restrict__ Wa_pair,
                                          int n1, float* __restrict__ d_out) {
    __shared__ float cs[16 * H];
    const int t = threadIdx.x, blk = blockIdx.x;

    if (blk == 0) {
        float4 z = make_float4(0.f, 0.f, 0.f, 0.f);
#pragma unroll
        for (int it = 0; it < 4; it++)         // c_mol region: 4096 floats
            ((float4*)d_out)[t + 256 * it] = z;
        if (t < 16)                            // flat row 0 = pad row
            ((float4*)(d_out + BS * H))[t] = z;
    }

    {
        int row = t >> 4, f4 = t & 15;
        int r = blk * 16 + row;
        float4 z = make_float4(0.f, 0.f, 0.f, 0.f);
        ((float4*)cs)[t] = (r < n1) ? ((const float4*)(inputs + (size_t)r * H))[f4] : z;
    }
    __syncthreads();

    const int eg = t & 63, rg = t >> 6;
    const int e0 = eg * 4;
    float4 acc[4];
#pragma unroll
    for (int m = 0; m < 4; m++) acc[m] = make_float4(0.f, 0.f, 0.f, 0.f);

#pragma unroll 8
    for (int h = 0; h < H; h++) {
        float4 w = __ldg((const float4*)(Wa_pair + h * E + e0));
#pragma unroll
        for (int m = 0; m < 4; m++) {
            float c = cs[(rg * 4 + m) * H + h];
            acc[m].x = fmaf(c, w.x, acc[m].x);
            acc[m].y = fmaf(c, w.y, acc[m].y);
            acc[m].z = fmaf(c, w.z, acc[m].z);
            acc[m].w = fmaf(c, w.w, acc[m].w);
        }
    }

#pragma unroll
    for (int m = 0; m < 4; m++) {
        int rr = blk * 16 + rg * 4 + m;
        if (rr < n1) {
            float* dst = g_u + (size_t)rr * E;
            float av[4] = {acc[m].x, acc[m].y, acc[m].z, acc[m].w};
#pragma unroll
            for (int c = 0; c < 4; c++) {
                int e = e0 + c;
                int l = e & 31, k = e >> 5;
                dst[(k >> 2) * 128 + 4 * l + (k & 3)] = av[c];
            }
        }
    }
}

// ---------------------------------------------------------------------------
// Kernel B: pairwise attention + c_sum -> g_csum (P layout).
// grid (64, 4): (b, quarter). 256 threads = 8 warps; each warp handles 2 i.
// dyn smem: up_s[64*256] + cbp_s[64*64] = 80 KB -> 2 blocks/SM.
// ---------------------------------------------------------------------------
__global__ void __launch_bounds__(256) kB(const float* __restrict__ inputs,
                                          const void* __restrict__ scope,
                                          const float* __restrict__ Wa_score) {
    extern __shared__ float sm[];
    float* up_s  = sm;              // 64 rows x 256 (P layout)
    float* cbp_s = sm + MA * E;     // 64 rows x 64 (quad-swizzled, see below)

    const bool is64 = scope_is64(scope);
    const int b = blockIdx.x, qq = blockIdx.y;
    const int t = threadIdx.x, l = t & 31, wid = t >> 5;

    // lane l owns e = l + 32k  (head n = l&3 lane-constant -> 3-shuffle reduce)
    float ws[8];
#pragma unroll
    for (int k = 0; k < 8; k++) ws[k] = __ldg(Wa_score + l + 32 * k);

    // stage u rows (already P-layout in gmem) via scope: float4 both sides
#pragma unroll
    for (int it = 0; it < 16; it++) {
        int Q = t + 256 * it;            // 64 rows * 64 quads
        int j = Q >> 6, qd = Q & 63;
        long long s = scope_at(scope, b * MA + j, is64);
        ((float4*)up_s)[Q] = ((const float4*)(g_u + (size_t)s * E))[qd];
    }
    // stage c: for h-group h (0..7), its m=0..3 quad sits at qA=2h+(h>=4),
    // m=4..7 at qB=2h+1-(h>=4)  => the 8 first-loads hit 8 distinct bank-quads.
#pragma unroll
    for (int it = 0; it < 4; it++) {
        int Q = t + 256 * it;            // 64 rows * 16 quads
        int j = Q >> 4, qd = Q & 15;
        long long s = scope_at(scope, b * MA + j, is64);
        const float* src = inputs + (size_t)s * H;
        int h = qd >> 1;
        int low = ((qd & 1) == (qd >> 3)) ? 0 : 4;   // inverse of the swap rule
        // careful: low half (m=0..3) iff (qd&1)==(qd>>3)
        int mb = ((qd & 1) == (qd >> 3)) ? 0 : 4;
        (void)low;
        float4 v;
        v.x = src[h + 8 * (mb + 0)];
        v.y = src[h + 8 * (mb + 1)];
        v.z = src[h + 8 * (mb + 2)];
        v.w = src[h + 8 * (mb + 3)];
        ((float4*)cbp_s)[Q] = v;
    }
    __syncthreads();

    const int h = l >> 2;
    const int qA = 2 * h + (h >> 2);        // h>=4 -> +1
    const int qB = 2 * h + 1 - (h >> 2);
    const int i0 = qq * 16 + wid, i1 = i0 + 8;

    const float4* uiA = (const float4*)(up_s + i0 * E);
    float4 A0 = uiA[l], A1 = uiA[32 + l];
    const float4* uiB = (const float4*)(up_s + i1 * E);
    float4 B0 = uiB[l], B1 = uiB[32 + l];

    unsigned long long csA[4] = {0, 0, 0, 0}, csB[4] = {0, 0, 0, 0};

#pragma unroll 4
    for (int j = 0; j < MA; j++) {
        const float4* ur = (const float4*)(up_s + j * E);
        float4 a0 = ur[l], a1 = ur[32 + l];
        float v, sA0, sA1, sB0, sB1;
        v = fmaxf(A0.x + a0.x, 0.f); sA0 = v * ws[0];
        v = fmaxf(A0.y + a0.y, 0.f); sA1 = v * ws[1];
        v = fmaxf(A0.z + a0.z, 0.f); sA0 = fmaf(v, ws[2], sA0);
        v = fmaxf(A0.w + a0.w, 0.f); sA1 = fmaf(v, ws[3], sA1);
        v = fmaxf(A1.x + a1.x, 0.f); sA0 = fmaf(v, ws[4], sA0);
        v = fmaxf(A1.y + a1.y, 0.f); sA1 = fmaf(v, ws[5], sA1);
        v = fmaxf(A1.z + a1.z, 0.f); sA0 = fmaf(v, ws[6], sA0);
        v = fmaxf(A1.w + a1.w, 0.f); sA1 = fmaf(v, ws[7], sA1);

        v = fmaxf(B0.x + a0.x, 0.f); sB0 = v * ws[0];
        v = fmaxf(B0.y + a0.y, 0.f); sB1 = v * ws[1];
        v = fmaxf(B0.z + a0.z, 0.f); sB0 = fmaf(v, ws[2], sB0);
        v = fmaxf(B0.w + a0.w, 0.f); sB1 = fmaf(v, ws[3], sB1);
        v = fmaxf(B1.x + a1.x, 0.f); sB0 = fmaf(v, ws[4], sB0);
        v = fmaxf(B1.y + a1.y, 0.f); sB1 = fmaf(v, ws[5], sB1);
        v = fmaxf(B1.z + a1.z, 0.f); sB0 = fmaf(v, ws[6], sB0);
        v = fmaxf(B1.w + a1.w, 0.f); sB1 = fmaf(v, ws[7], sB1);

        float sA = sA0 + sA1, sB = sB0 + sB1;
        sA += __shfl_xor_sync(0xffffffffu, sA, 4);
        sB += __shfl_xor_sync(0xffffffffu, sB, 4);
        sA += __shfl_xor_sync(0xffffffffu, sA, 8);
        sB += __shfl_xor_sync(0xffffffffu, sB, 8);
        sA += __shfl_xor_sync(0xffffffffu, sA, 16);
        sB += __shfl_xor_sync(0xffffffffu, sB, 16);

        unsigned long long attA = pack2(sigmoid_fast(sA));
        unsigned long long attB = pack2(sigmoid_fast(sB));

        ulonglong2 c01 = *(const ulonglong2*)(cbp_s + j * H + 4 * qA);
        ulonglong2 c23 = *(const ulonglong2*)(cbp_s + j * H + 4 * qB);
        FMA2(csA[0], attA, c01.x);  FMA2(csA[1], attA, c01.y);
        FMA2(csA[2], attA, c23.x);  FMA2(csA[3], attA, c23.y);
        FMA2(csB[0], attB, c01.x);  FMA2(csB[1], attB, c01.y);
        FMA2(csB[2], attB, c23.x);  FMA2(csB[3], attB, c23.y);
    }

    // store csum rows in P layout: lane l -> quads l and 32+l
    {
        ulonglong2 v;
        float* oA = g_csum + (size_t)(b * MA + i0) * E;
        v.x = csA[0]; v.y = csA[1]; *(ulonglong2*)(oA + 4 * l) = v;
        v.x = csA[2]; v.y = csA[3]; *(ulonglong2*)(oA + 128 + 4 * l) = v;
        float* oB = g_csum + (size_t)(b * MA + i1) * E;
        v.x = csB[0]; v.y = csB[1]; *(ulonglong2*)(oB + 4 * l) = v;
        v.x = csB[2]; v.y = csB[3]; *(ulonglong2*)(oB + 128 + 4 * l) = v;
    }
}

// ---------------------------------------------------------------------------
// Kernel D: projection A = csum @ Wp, scatter flat rows, and c_mol via REDG.
// grid 128 = (b, half of 32 rows). 256 threads; thread = 2 rows x 4 cols.
// dyn smem: wp_s[256*64] (P-permuted rows) + cs_s[32*256] = 96 KB.
// ---------------------------------------------------------------------------
__global__ void __launch_bounds__(256) kD(const void* __restrict__ scope,
                                          const float* __restrict__ Wp,
                                          float* __restrict__ d_out) {
    extern __shared__ float sm[];
    float* wp_s = sm;            // 256 x 64, row p holds Wp row e(p)
    float* cs_s = sm + E * H;    // 32 x 256 (P layout)

    const bool is64 = scope_is64(scope);
    const int b = blockIdx.x >> 1, half = blockIdx.x & 1;
    const int t = threadIdx.x;

    // stage Wp permuted to P: e(p) with half=p>>7, r=p&127: e = (r>>2) + 32*((r&3)+4*half)
#pragma unroll
    for (int it = 0; it < 16; it++) {
        int q = t + 256 * it;            // 256 p * 16 quads
        int p = q >> 4, quad = q & 15;
        int hf = p >> 7, r = p & 127;
        int e = (r >> 2) + 32 * ((r & 3) + 4 * hf);
        ((float4*)wp_s)[q] = __ldg(((const float4*)Wp) + e * 16 + quad);
    }
    // stage 32 csum rows (contiguous copy; layout already matches wp_s)
    {
        const float4* src = (const float4*)(g_csum + (size_t)(b * MA + half * 32) * E);
#pragma unroll
        for (int it = 0; it < 8; it++) ((float4*)cs_s)[t + 256 * it] = src[t + 256 * it];
    }
    __syncthreads();

    const int cg = t & 15, rg = t >> 4;   // 16 col-groups x 16 row-groups
    const int c0 = cg * 4, r0 = rg * 2;
    unsigned long long accA01 = 0, accA23 = 0, accB01 = 0, accB23 = 0;

#pragma unroll 4
    for (int p = 0; p < E; p++) {
        ulonglong2 w = ((const ulonglong2*)wp_s)[p * 16 + cg];
        unsigned long long ca = pack2(cs_s[r0 * E + p]);
        unsigned long long cb = pack2(cs_s[(r0 + 1) * E + p]);
        FMA2(accA01, ca, w.x);  FMA2(accA23, ca, w.y);
        FMA2(accB01, cb, w.x);  FMA2(accB23, cb, w.y);
    }

    // scatter flat rows: flat[scope[b*64+r]] = A[b,r]  (scope==0 -> pad, skip)
    float* flat = d_out + BS * H;
    {
        int r = half * 32 + r0;
        long long s0 = scope_at(scope, b * MA + r, is64);
        long long s1 = scope_at(scope, b * MA + r + 1, is64);
        ulonglong2 vA; vA.x = accA01; vA.y = accA23;   // == float4 {c0..c3}
        ulonglong2 vB; vB.x = accB01; vB.y = accB23;
        if (s0 > 0) *((ulonglong2*)(flat + s0 * H + c0)) = vA;
        if (s1 > 0) *((ulonglong2*)(flat + s1 * H + c0)) = vB;
    }

    __syncthreads();                     // done reading cs_s -> reuse as reduction buf
    float* red = cs_s;                   // 16 x 64
    {
        unsigned long long s01, s23;
        asm("add.rn.f32x2 %0, %1, %2;" : "=l"(s01) : "l"(accA01), "l"(accB01));
        asm("add.rn.f32x2 %0, %1, %2;" : "=l"(s23) : "l"(accA23), "l"(accB23));
        ulonglong2 v; v.x = s01; v.y = s23;
        *((ulonglong2*)(red + rg * H + c0)) = v;
    }
    __syncthreads();
    if (t < H) {
        float s = 0.f;
#pragma unroll
        for (int g = 0; g < 16; g++) s += red[g * H + t];
        atomicAdd(d_out + b * H + t, s);   // exactly 2 contributors: deterministic
    }
}

// ---------------------------------------------------------------------------
extern "C" void kernel_launch(void* const* d_in, const int* in_sizes, int n_in,
                              void* d_out, int out_size) {
    const float* inputs   = (const float*)d_in[0];
    const void*  scope    = d_in[1];
    // d_in[2] = scope_rev_tensor (unused: scatter via scope is its inverse)
    const float* Wa_pair  = (const float*)d_in[3];
    const float* Wa_score = (const float*)d_in[4];
    const float* Wp       = (const float*)d_in[5];
    float* out = (float*)d_out;

    const int n1 = in_sizes[0] / H;                           // N+1 flat rows
    const int smemB = (MA * E + MA * H) * (int)sizeof(float); // 81920 B
    const int smemD = (E * H + 32 * E) * (int)sizeof(float);  // 98304 B
    cudaFuncSetAttribute(kB, cudaFuncAttributeMaxDynamicSharedMemorySize, smemB);
    cudaFuncSetAttribute(kD, cudaFuncAttributeMaxDynamicSharedMemorySize, smemD);

    kA<<<(n1 + 15) / 16, 256>>>(inputs, Wa_pair, n1, out);
    kB<<<dim3(BS, 4), 256, smemB>>>(inputs, scope, Wa_score);
    kD<<<BS * 2, 256, smemD>>>(scope, Wp, out);
}